// round 17
// baseline (speedup 1.0000x reference)
#include <cuda_runtime.h>
#include <cstdint>

#define EPSF 1e-7f
typedef unsigned long long u64t;

constexpr int Bb = 32;
constexpr int Ii = 32;
constexpr int Oo = 64;
constexpr int Pp = 16;
constexpr int Nn = 2048;
constexpr int CHUNKS = 16;   // 4 spatial per block
constexpr int ROWS = 128;    // 4 spatial * 32 i
constexpr int WS = 20;       // padded stride for mean/inv (conflict-free LDS128)
constexpr int REC = 33;      // floats per (o) partial record: A0 + 16 A1 + 16 A2

// Global scratch (device globals; no cudaMalloc allowed)
__device__ float g_mean[Bb][Oo][Pp];
__device__ float g_inv2var[Bb][Oo][Pp];
__device__ float g_ll[Bb][Oo];              // log(act+eps) - lsum - max_o(.)  (pre-shifted)
__device__ ulonglong2 g_wT2[Ii * 4 * Oo];   // W: [ic][k][o] -> {pair(c0,c1), pair(c2,c3)}
__device__ float g_part[(size_t)Bb * CHUNKS * Oo * REC];   // per-(b,chunk) partials

// ---- f32x2 packed helpers ----
__device__ __forceinline__ u64t pk2(float lo, float hi) {
    u64t r; asm("mov.b64 %0,{%1,%2};" : "=l"(r) : "f"(lo), "f"(hi)); return r;
}
__device__ __forceinline__ void up2(u64t a, float& lo, float& hi) {
    asm("mov.b64 {%0,%1},%2;" : "=f"(lo), "=f"(hi) : "l"(a));
}
__device__ __forceinline__ u64t fma2(u64t a, u64t b, u64t c) {
    u64t d; asm("fma.rn.f32x2 %0,%1,%2,%3;" : "=l"(d) : "l"(a), "l"(b), "l"(c)); return d;
}
__device__ __forceinline__ u64t add2(u64t a, u64t b) {
    u64t d; asm("add.rn.f32x2 %0,%1,%2;" : "=l"(d) : "l"(a), "l"(b)); return d;
}
__device__ __forceinline__ u64t mul2(u64t a, u64t b) {
    u64t d; asm("mul.rn.f32x2 %0,%1,%2;" : "=l"(d) : "l"(a), "l"(b)); return d;
}
// ---- warp sum reduction (redux.sync.f32 not in sm_103 ISA) ----
__device__ __forceinline__ float warp_add(float v) {
    #pragma unroll
    for (int off = 16; off >= 1; off >>= 1)
        v += __shfl_xor_sync(0xffffffffu, v, off);
    return v;
}
// ---- named barrier for a 2-warp pair ----
__device__ __forceinline__ void pair_bar(int id) {
    asm volatile("bar.sync %0, 64;" :: "r"(id) : "memory");
}

// One-time prep: transpose W to o-contiguous dual-pairs.
__global__ void prep_kernel(const float* __restrict__ w) {
    int idx = blockIdx.x * 256 + threadIdx.x;   // grid covers 8192
    if (idx < Ii * 4 * Oo) {
        int o = idx & 63, k = (idx >> 6) & 3, ic = idx >> 8;
        const float4 s = *(const float4*)(w + ((ic * Oo + o) * 16 + k * 4));
        ulonglong2 d;
        d.x = ((u64t)__float_as_uint(s.y) << 32) | __float_as_uint(s.x);
        d.y = ((u64t)__float_as_uint(s.w) << 32) | __float_as_uint(s.z);
        g_wT2[idx] = d;
    }
}

// Fused stats kernel: 256 thr = 8 warps = 4 spatial x 2 o-halves.
// Each warp owns 32 o for all 32 ic: half the registers, half the chain.
// Softmax denominator spans the warp pair via double-buffered smem + named bar.
// No atomics, no warp_max (g_ll pre-shifted so zz <= 0).
template<bool FIRST>
__global__ __launch_bounds__(256, 3)
void stats_kernel(const float* __restrict__ gpose,
                  const float* __restrict__ gact)
{
    __shared__ float sm[8448];       // overlay: main phase 4800 / partial phase 8448
    __shared__ float sEx[2][8];      // softmax half-sums, double-buffered per warp
    float* sMean = sm;               // negated mean, stride WS (1280)
    float* sInv  = sm + 1280;        // 1/(2 var), stride WS (1280)
    float* sLL   = sm + 2560;        // (64)
    float* sPose = sm + 2624;        // raw pose rows (2048)
    float* sAct  = sm + 4672;        // (128)

    const int tid   = threadIdx.x;
    const int b     = blockIdx.y;
    const int chunk = blockIdx.x;

    // ---- stage pose + act ----
    const float4* gp4 = (const float4*)(gpose + ((size_t)(b * Nn + chunk * ROWS)) * 16);
    #pragma unroll
    for (int i = 0; i < 2; i++)
        ((float4*)sPose)[tid + 256 * i] = gp4[tid + 256 * i];
    if (tid < ROWS) sAct[tid] = gact[b * Nn + chunk * ROWS + tid];

    if (!FIRST) {
        for (int idx = tid; idx < Oo * Pp; idx += 256) {
            int o = idx >> 4, p = idx & 15;
            sMean[o * WS + p] = -g_mean[b][o][p];
            sInv[o * WS + p]  = g_inv2var[b][o][p];
        }
        if (tid < Oo) sLL[tid] = g_ll[b][tid];
    }
    __syncthreads();

    const int wid  = tid >> 5;
    const int lane = tid & 31;
    const int spl  = wid >> 1;                 // local spatial 0..3
    const int half = wid & 1;                  // o-half
    const int o    = half * 32 + lane;
    const int barid = 1 + spl;                 // named barrier per pair
    const int sp   = chunk * 4 + spl;          // global spatial [0,64)
    const float chv = ((sp >> 3) + 0.5f) * 0.125f;
    const float cwv = ((sp & 7) + 0.5f) * 0.125f;

    float ll_o = 0.0f;
    if (!FIRST) ll_o = sLL[o];
    const ulonglong2* mr = (const ulonglong2*)&sMean[o * WS];
    const ulonglong2* ir = (const ulonglong2*)&sInv[o * WS];

    u64t A1[8], A2[8];
    float A0 = 0.0f;
    #pragma unroll
    for (int r2 = 0; r2 < 8; r2++) { A1[r2] = 0ull; A2[r2] = 0ull; }

    for (int ic = 0; ic < Ii; ic++) {
        const int r = spl * 32 + ic;

        // pose row -> 16 floats (4 broadcast LDS128, reused across k)
        float pr[16];
        {
            const float4* pp = (const float4*)&sPose[r * 16];
            #pragma unroll
            for (int q = 0; q < 4; q++) {
                float4 t = pp[q];
                pr[q*4+0] = t.x; pr[q*4+1] = t.y; pr[q*4+2] = t.z; pr[q*4+3] = t.w;
            }
        }
        const float a_n = sAct[r];

        // votes for this warp's o-half (4 independent LDG.128)
        u64t va[8];
        va[0] = pk2(chv, cwv);
        #pragma unroll
        for (int r2 = 1; r2 < 8; r2++) va[r2] = 0ull;

        const ulonglong2* wb = g_wT2 + ic * 256 + o;
        #pragma unroll
        for (int k = 0; k < 4; k++) {
            ulonglong2 wk = __ldg(wb + k * 64);
            #pragma unroll
            for (int a = 0; a < 4; a++) {
                u64t pa = pk2(pr[a*4+k], pr[a*4+k]);
                va[a*2+0] = fma2(pa, wk.x, va[a*2+0]);
                va[a*2+1] = fma2(pa, wk.y, va[a*2+1]);
            }
        }

        float rrp;
        if (!FIRST) {
            u64t acc = 0ull;
            #pragma unroll
            for (int q = 0; q < 4; q++) {
                ulonglong2 m  = mr[q], iv = ir[q];
                u64t d0 = add2(va[q*2+0], m.x);      // mean pre-negated
                acc = fma2(mul2(d0, d0), iv.x, acc);
                u64t d1 = add2(va[q*2+1], m.y);
                acc = fma2(mul2(d1, d1), iv.y, acc);
            }
            float al, ah; up2(acc, al, ah);
            // g_ll pre-shifted by max_o -> zz <= 0, exp safe with no warp max
            float e = __expf(ll_o - (al + ah));
            float sH = warp_add(e);                   // sum over this half's 32 o
            if (lane == 0) sEx[ic & 1][wid] = sH;
            pair_bar(barid);                          // drains STS; pair lockstep
            float s = sH + sEx[ic & 1][wid ^ 1];      // + partner half
            rrp = e * __fdividef(a_n, s);
        } else {
            rrp = a_n * (1.0f / 64.0f);
        }

        A0 += rrp;
        u64t rp = pk2(rrp, rrp);
        #pragma unroll
        for (int r2 = 0; r2 < 8; r2++) {
            u64t t = mul2(rp, va[r2]);
            A1[r2] = add2(A1[r2], t);
            A2[r2] = fma2(t, va[r2], A2[r2]);
        }
    }

    // ---- NO-ATOMIC reduction: STS partials, tree-sum over spatial, STG ----
    __syncthreads();               // everyone done with sMean/sPose etc.
    float* sPart = sm;             // reuse ALL smem: [wid][lane][REC]
    {
        float* rec = &sPart[(wid * 32 + lane) * REC];
        rec[0] = A0;
        #pragma unroll
        for (int r2 = 0; r2 < 8; r2++) {
            float lo, hi;
            up2(A1[r2], lo, hi);
            rec[1 + 2*r2]  = lo;
            rec[2 + 2*r2]  = hi;
            up2(A2[r2], lo, hi);
            rec[17 + 2*r2] = lo;
            rec[18 + 2*r2] = hi;
        }
    }
    __syncthreads();

    float* gout = g_part + ((size_t)(b * CHUNKS + chunk)) * (Oo * REC);
    for (int e = tid; e < Oo * REC; e += 256) {
        int oo = e / REC, j = e - oo * REC;
        int hf = oo >> 5, ol = oo & 31;
        float s = sPart[((0 * 2 + hf) * 32 + ol) * REC + j]
                + sPart[((1 * 2 + hf) * 32 + ol) * REC + j]
                + sPart[((2 * 2 + hf) * 32 + ol) * REC + j]
                + sPart[((3 * 2 + hf) * 32 + ol) * REC + j];
        gout[oo * REC + j] = s;
    }
}

// finalize: sum 16 chunk partials per (b,o), then EM finalize math.
// Stores g_ll pre-shifted by its per-batch max so stats needs no warp_max.
__global__ __launch_bounds__(64)
void finalize_kernel(int it,
                     const float* __restrict__ beta_v,
                     const float* __restrict__ beta_a,
                     float* __restrict__ out)
{
    __shared__ float sCost[Oo];
    __shared__ float sLLs[Oo];
    const int b = blockIdx.x;
    const int o = threadIdx.x;

    const float* pb = g_part + (size_t)b * CHUNKS * (Oo * REC) + o * REC;
    float s0 = 0.0f;
    float s1[16], s2[16];
    #pragma unroll
    for (int p = 0; p < 16; p++) { s1[p] = 0.0f; s2[p] = 0.0f; }
    for (int ch = 0; ch < CHUNKS; ch++) {
        const float* rec = pb + ch * (Oo * REC);
        s0 += __ldg(&rec[0]);
        #pragma unroll
        for (int p = 0; p < 16; p++) {
            s1[p] += __ldg(&rec[1 + p]);
            s2[p] += __ldg(&rec[17 + p]);
        }
    }

    const float inv_rps = 1.0f / s0;
    float mean[16], inv2v[16];
    float lsum = 0.0f;
    #pragma unroll
    for (int p = 0; p < 16; p++) {
        float m = s1[p] * inv_rps;
        float var = s2[p] * inv_rps - m * m;
        var = fmaxf(var, 0.0f);
        float sd = sqrtf(var);
        mean[p] = m;
        inv2v[p] = 0.5f / var;
        lsum += __logf(sd + EPSF);
    }
    const float cost = (16.0f * beta_v[o] + lsum) * s0;
    sCost[o] = cost;
    __syncthreads();

    float cm = 0.0f;
    for (int q = 0; q < Oo; q++) cm += sCost[q];
    cm *= (1.0f / 64.0f);
    float cv = 0.0f;
    for (int q = 0; q < Oo; q++) { float d = sCost[q] - cm; cv += d * d; }
    const float cstd = sqrtf(cv * (1.0f / 64.0f));

    const float inv_temp = 1.0f + (float)it;
    const float x = inv_temp * (beta_a[o] + (cm - cost) / (cstd + EPSF));
    const float oact = 1.0f / (1.0f + __expf(-x));

    if (it < 2) {
        const float llv = __logf(oact + EPSF) - lsum;
        sLLs[o] = llv;
        #pragma unroll
        for (int p = 0; p < 16; p++) {
            g_mean[b][o][p] = mean[p];
            g_inv2var[b][o][p] = inv2v[p];
        }
        __syncthreads();
        float M = sLLs[0];
        for (int q = 1; q < Oo; q++) M = fmaxf(M, sLLs[q]);
        g_ll[b][o] = llv - M;     // pre-shift: zz = ll - dist <= 0 in stats
    } else {
        #pragma unroll
        for (int p = 0; p < 16; p++) out[(b * Oo + o) * 16 + p] = mean[p];
        out[Bb * Oo * Pp + b * Oo + o] = oact;
    }
}

extern "C" void kernel_launch(void* const* d_in, const int* in_sizes, int n_in,
                              void* d_out, int out_size)
{
    const float* pose = (const float*)d_in[0];
    const float* act  = (const float*)d_in[1];
    const float* w    = (const float*)d_in[2];
    const float* bv   = (const float*)d_in[3];
    const float* ba   = (const float*)d_in[4];
    float* out = (float*)d_out;

    dim3 grid(CHUNKS, Bb);

    prep_kernel<<<32, 256>>>(w);
    stats_kernel<true><<<grid, 256>>>(pose, act);
    finalize_kernel<<<Bb, 64>>>(0, bv, ba, out);
    stats_kernel<false><<<grid, 256>>>(pose, act);
    finalize_kernel<<<Bb, 64>>>(1, bv, ba, out);
    stats_kernel<false><<<grid, 256>>>(pose, act);
    finalize_kernel<<<Bb, 64>>>(2, bv, ba, out);
}